// round 6
// baseline (speedup 1.0000x reference)
#include <cuda_runtime.h>
#include <cuda_bf16.h>
#include <cstdint>

// out[r] = tanh((x0*x1 + sin(x2))*exp(-|x3|) + x4/(x5^2+exp(x6)) - x7)
// Persistent grid-stride: 1184 CTAs (148 SMs x 8), each iteration handles
// 1024 rows/block (4 rows/thread, warp-contiguous => 32B lane stride),
// 8 front-batched LDG.128.CS per thread. No wave transitions.

__global__ __launch_bounds__(256) void expr_kernel(
    const float4* __restrict__ in,   // N_ROWS*2 float4
    float* __restrict__ out,         // N_ROWS floats
    int n_rows)
{
    const int tid = threadIdx.x;
    const int stride = gridDim.x * 1024;     // rows covered per grid sweep

    for (int base = blockIdx.x * 1024 + tid; base < n_rows; base += stride) {
        const int r0 = base;
        const int r1 = base + 256;
        const int r2 = base + 512;
        const int r3 = base + 768;

        if (r3 < n_rows) {
            float4 a0 = __ldcs(in + 2 * r0);
            float4 b0 = __ldcs(in + 2 * r0 + 1);
            float4 a1 = __ldcs(in + 2 * r1);
            float4 b1 = __ldcs(in + 2 * r1 + 1);
            float4 a2 = __ldcs(in + 2 * r2);
            float4 b2 = __ldcs(in + 2 * r2 + 1);
            float4 a3 = __ldcs(in + 2 * r3);
            float4 b3 = __ldcs(in + 2 * r3 + 1);

            float e0 = (a0.x * a0.y + __sinf(a0.z)) * __expf(-fabsf(a0.w))
                     + __fdividef(b0.x, b0.y * b0.y + __expf(b0.z)) - b0.w;
            float e1 = (a1.x * a1.y + __sinf(a1.z)) * __expf(-fabsf(a1.w))
                     + __fdividef(b1.x, b1.y * b1.y + __expf(b1.z)) - b1.w;
            float e2 = (a2.x * a2.y + __sinf(a2.z)) * __expf(-fabsf(a2.w))
                     + __fdividef(b2.x, b2.y * b2.y + __expf(b2.z)) - b2.w;
            float e3 = (a3.x * a3.y + __sinf(a3.z)) * __expf(-fabsf(a3.w))
                     + __fdividef(b3.x, b3.y * b3.y + __expf(b3.z)) - b3.w;

            __stcs(out + r0, tanhf(e0));
            __stcs(out + r1, tanhf(e1));
            __stcs(out + r2, tanhf(e2));
            __stcs(out + r3, tanhf(e3));
        } else {
            #pragma unroll
            for (int k = 0; k < 4; k++) {
                int r = base + k * 256;
                if (r < n_rows) {
                    float4 a = __ldcs(in + 2 * r);
                    float4 b = __ldcs(in + 2 * r + 1);
                    float e = (a.x * a.y + __sinf(a.z)) * __expf(-fabsf(a.w))
                            + __fdividef(b.x, b.y * b.y + __expf(b.z)) - b.w;
                    __stcs(out + r, tanhf(e));
                }
            }
        }
    }
}

extern "C" void kernel_launch(void* const* d_in, const int* in_sizes, int n_in,
                              void* d_out, int out_size)
{
    const float4* in = (const float4*)d_in[0];
    float* out = (float*)d_out;

    int n_rows = out_size;          // 8388608
    int threads = 256;
    int blocks = 148 * 8;           // persistent: one wave, 8 CTAs/SM
    expr_kernel<<<blocks, threads>>>(in, out, n_rows);
}

// round 7
// speedup vs baseline: 1.0054x; 1.0054x over previous
#include <cuda_runtime.h>
#include <cuda_bf16.h>
#include <cstdint>

// out[r] = tanh((x0*x1 + sin(x2))*exp(-|x3|) + x4/(x5^2+exp(x6)) - x7)
// Flat grid (no persistence — grid-stride serialized the memory phases).
// 8 rows/thread, warp-contiguous mapping (row = base + tid + k*256) keeps the
// 32B-lane-stride coalescing; 16 front-batched LDG.128.CS -> MLP=16/thread.

__device__ __forceinline__ float expr1(float4 a, float4 b)
{
    return tanhf((a.x * a.y + __sinf(a.z)) * __expf(-fabsf(a.w))
               + __fdividef(b.x, b.y * b.y + __expf(b.z)) - b.w);
}

__global__ __launch_bounds__(256) void expr_kernel(
    const float4* __restrict__ in,   // N_ROWS*2 float4
    float* __restrict__ out,         // N_ROWS floats
    int n_rows)
{
    const int tid = threadIdx.x;
    const int base = blockIdx.x * 2048 + tid;   // 2048 rows per block

    if (base + 1792 < n_rows) {
        // Front-batch all 16 loads for maximum memory-level parallelism.
        float4 a0 = __ldcs(in + 2 * (base +    0));
        float4 b0 = __ldcs(in + 2 * (base +    0) + 1);
        float4 a1 = __ldcs(in + 2 * (base +  256));
        float4 b1 = __ldcs(in + 2 * (base +  256) + 1);
        float4 a2 = __ldcs(in + 2 * (base +  512));
        float4 b2 = __ldcs(in + 2 * (base +  512) + 1);
        float4 a3 = __ldcs(in + 2 * (base +  768));
        float4 b3 = __ldcs(in + 2 * (base +  768) + 1);
        float4 a4 = __ldcs(in + 2 * (base + 1024));
        float4 b4 = __ldcs(in + 2 * (base + 1024) + 1);
        float4 a5 = __ldcs(in + 2 * (base + 1280));
        float4 b5 = __ldcs(in + 2 * (base + 1280) + 1);
        float4 a6 = __ldcs(in + 2 * (base + 1536));
        float4 b6 = __ldcs(in + 2 * (base + 1536) + 1);
        float4 a7 = __ldcs(in + 2 * (base + 1792));
        float4 b7 = __ldcs(in + 2 * (base + 1792) + 1);

        __stcs(out + base +    0, expr1(a0, b0));
        __stcs(out + base +  256, expr1(a1, b1));
        __stcs(out + base +  512, expr1(a2, b2));
        __stcs(out + base +  768, expr1(a3, b3));
        __stcs(out + base + 1024, expr1(a4, b4));
        __stcs(out + base + 1280, expr1(a5, b5));
        __stcs(out + base + 1536, expr1(a6, b6));
        __stcs(out + base + 1792, expr1(a7, b7));
    } else {
        #pragma unroll
        for (int k = 0; k < 8; k++) {
            int r = base + k * 256;
            if (r < n_rows) {
                float4 a = __ldcs(in + 2 * r);
                float4 b = __ldcs(in + 2 * r + 1);
                __stcs(out + r, expr1(a, b));
            }
        }
    }
}

extern "C" void kernel_launch(void* const* d_in, const int* in_sizes, int n_in,
                              void* d_out, int out_size)
{
    const float4* in = (const float4*)d_in[0];
    float* out = (float*)d_out;

    int n_rows = out_size;   // 8388608
    int threads = 256;
    int rows_per_block = threads * 8;
    int blocks = (n_rows + rows_per_block - 1) / rows_per_block;  // 4096
    expr_kernel<<<blocks, threads>>>(in, out, n_rows);
}

// round 9
// speedup vs baseline: 1.0136x; 1.0082x over previous
#include <cuda_runtime.h>
#include <cuda_bf16.h>
#include <cstdint>

// out[r] = tanh((x0*x1 + sin(x2))*exp(-|x3|) + x4/(x5^2+exp(x6)) - x7)
// R4 memory structure (best: MLP=8/thread, warp-contiguous 32B lane stride),
// block=512 for coarser CTA granularity. Flat grid, 4 rows/thread,
// 8 front-batched LDG.128.CS per thread.

__device__ __forceinline__ float expr1(float4 a, float4 b)
{
    return tanhf((a.x * a.y + __sinf(a.z)) * __expf(-fabsf(a.w))
               + __fdividef(b.x, b.y * b.y + __expf(b.z)) - b.w);
}

__global__ __launch_bounds__(512) void expr_kernel(
    const float4* __restrict__ in,   // N_ROWS*2 float4
    float* __restrict__ out,         // N_ROWS floats
    int n_rows)
{
    const int tid = threadIdx.x;
    const int base = blockIdx.x * 2048 + tid;   // 2048 rows per block

    const int r0 = base;
    const int r1 = base + 512;
    const int r2 = base + 1024;
    const int r3 = base + 1536;

    if (r3 < n_rows) {
        // Front-batch all 8 loads for MLP=8.
        float4 a0 = __ldcs(in + 2 * r0);
        float4 b0 = __ldcs(in + 2 * r0 + 1);
        float4 a1 = __ldcs(in + 2 * r1);
        float4 b1 = __ldcs(in + 2 * r1 + 1);
        float4 a2 = __ldcs(in + 2 * r2);
        float4 b2 = __ldcs(in + 2 * r2 + 1);
        float4 a3 = __ldcs(in + 2 * r3);
        float4 b3 = __ldcs(in + 2 * r3 + 1);

        __stcs(out + r0, expr1(a0, b0));
        __stcs(out + r1, expr1(a1, b1));
        __stcs(out + r2, expr1(a2, b2));
        __stcs(out + r3, expr1(a3, b3));
    } else {
        #pragma unroll
        for (int k = 0; k < 4; k++) {
            int r = base + k * 512;
            if (r < n_rows) {
                float4 a = __ldcs(in + 2 * r);
                float4 b = __ldcs(in + 2 * r + 1);
                __stcs(out + r, expr1(a, b));
            }
        }
    }
}

extern "C" void kernel_launch(void* const* d_in, const int* in_sizes, int n_in,
                              void* d_out, int out_size)
{
    const float4* in = (const float4*)d_in[0];
    float* out = (float*)d_out;

    int n_rows = out_size;   // 8388608
    int threads = 512;
    int rows_per_block = threads * 4;
    int blocks = (n_rows + rows_per_block - 1) / rows_per_block;  // 4096
    expr_kernel<<<blocks, threads>>>(in, out, n_rows);
}

// round 10
// speedup vs baseline: 1.0450x; 1.0309x over previous
#include <cuda_runtime.h>
#include <cuda_bf16.h>
#include <cstdint>

// out[r] = tanh((x0*x1 + sin(x2))*exp(-|x3|) + x4/(x5^2+exp(x6)) - x7)
// Final (R4 config, best measured): flat grid, block=256, 4 rows/thread with
// warp-contiguous mapping (row = base + tid + k*256 => 32B lane stride, 2x
// L1 wavefronts), 8 front-batched LDG.128.CS per thread (MLP=8), coalesced
// STG.32.CS. DRAM-streaming-bound at ~84% of HBM spec — measured roofline.

__device__ __forceinline__ float expr1(float4 a, float4 b)
{
    return tanhf((a.x * a.y + __sinf(a.z)) * __expf(-fabsf(a.w))
               + __fdividef(b.x, b.y * b.y + __expf(b.z)) - b.w);
}

__global__ __launch_bounds__(256) void expr_kernel(
    const float4* __restrict__ in,   // N_ROWS*2 float4
    float* __restrict__ out,         // N_ROWS floats
    int n_rows)
{
    const int tid = threadIdx.x;
    const int base = blockIdx.x * 1024 + tid;   // 1024 rows per block

    const int r0 = base;
    const int r1 = base + 256;
    const int r2 = base + 512;
    const int r3 = base + 768;

    if (r3 < n_rows) {
        // Front-batch all 8 loads for MLP=8.
        float4 a0 = __ldcs(in + 2 * r0);
        float4 b0 = __ldcs(in + 2 * r0 + 1);
        float4 a1 = __ldcs(in + 2 * r1);
        float4 b1 = __ldcs(in + 2 * r1 + 1);
        float4 a2 = __ldcs(in + 2 * r2);
        float4 b2 = __ldcs(in + 2 * r2 + 1);
        float4 a3 = __ldcs(in + 2 * r3);
        float4 b3 = __ldcs(in + 2 * r3 + 1);

        __stcs(out + r0, expr1(a0, b0));
        __stcs(out + r1, expr1(a1, b1));
        __stcs(out + r2, expr1(a2, b2));
        __stcs(out + r3, expr1(a3, b3));
    } else {
        #pragma unroll
        for (int k = 0; k < 4; k++) {
            int r = base + k * 256;
            if (r < n_rows) {
                float4 a = __ldcs(in + 2 * r);
                float4 b = __ldcs(in + 2 * r + 1);
                __stcs(out + r, expr1(a, b));
            }
        }
    }
}

extern "C" void kernel_launch(void* const* d_in, const int* in_sizes, int n_in,
                              void* d_out, int out_size)
{
    const float4* in = (const float4*)d_in[0];
    float* out = (float*)d_out;

    int n_rows = out_size;   // 8388608
    int threads = 256;
    int rows_per_block = threads * 4;
    int blocks = (n_rows + rows_per_block - 1) / rows_per_block;  // 8192
    expr_kernel<<<blocks, threads>>>(in, out, n_rows);
}

// round 11
// speedup vs baseline: 1.0878x; 1.0410x over previous
#include <cuda_runtime.h>
#include <cuda_bf16.h>
#include <cstdint>

// out[r] = tanh((x0*x1 + sin(x2))*exp(-|x3|) + x4/(x5^2+exp(x6)) - x7)
// FINAL: flat grid, block=256, 4 rows/thread, warp-contiguous mapping
// (row = base + tid + k*256 => 32B lane stride), 8 front-batched LDG.128.CS
// (MLP=8), coalesced STG.32.CS. DRAM-streaming-bound at ~85% of HBM spec —
// measured roofline across MLP{2,4,8,16}, persistent, and block-size sweeps.

__device__ __forceinline__ float expr1(float4 a, float4 b)
{
    return tanhf((a.x * a.y + __sinf(a.z)) * __expf(-fabsf(a.w))
               + __fdividef(b.x, b.y * b.y + __expf(b.z)) - b.w);
}

__global__ __launch_bounds__(256) void expr_kernel(
    const float4* __restrict__ in,   // N_ROWS*2 float4
    float* __restrict__ out,         // N_ROWS floats
    int n_rows)
{
    const int tid = threadIdx.x;
    const int base = blockIdx.x * 1024 + tid;   // 1024 rows per block

    const int r0 = base;
    const int r1 = base + 256;
    const int r2 = base + 512;
    const int r3 = base + 768;

    if (__builtin_expect(r3 < n_rows, 1)) {
        // Hot path (all CTAs when n_rows % 1024 == 0): 8 front-batched loads.
        float4 a0 = __ldcs(in + 2 * r0);
        float4 b0 = __ldcs(in + 2 * r0 + 1);
        float4 a1 = __ldcs(in + 2 * r1);
        float4 b1 = __ldcs(in + 2 * r1 + 1);
        float4 a2 = __ldcs(in + 2 * r2);
        float4 b2 = __ldcs(in + 2 * r2 + 1);
        float4 a3 = __ldcs(in + 2 * r3);
        float4 b3 = __ldcs(in + 2 * r3 + 1);

        __stcs(out + r0, expr1(a0, b0));
        __stcs(out + r1, expr1(a1, b1));
        __stcs(out + r2, expr1(a2, b2));
        __stcs(out + r3, expr1(a3, b3));
    } else {
        // Generic tail (unused at N_ROWS = 8388608).
        #pragma unroll
        for (int k = 0; k < 4; k++) {
            int r = base + k * 256;
            if (r < n_rows) {
                float4 a = __ldcs(in + 2 * r);
                float4 b = __ldcs(in + 2 * r + 1);
                __stcs(out + r, expr1(a, b));
            }
        }
    }
}

extern "C" void kernel_launch(void* const* d_in, const int* in_sizes, int n_in,
                              void* d_out, int out_size)
{
    const float4* in = (const float4*)d_in[0];
    float* out = (float*)d_out;

    int n_rows = out_size;   // 8388608
    int threads = 256;
    int rows_per_block = threads * 4;
    int blocks = (n_rows + rows_per_block - 1) / rows_per_block;  // 8192
    expr_kernel<<<blocks, threads>>>(in, out, n_rows);
}